// round 5
// baseline (speedup 1.0000x reference)
#include <cuda_runtime.h>
#include <cuda_fp16.h>
#include <mma.h>
#include <math.h>
#include <stdint.h>

using namespace nvcuda;

// Problem constants
#define B_    128
#define D_    2048
#define C_    16522
#define CP    16640          // padded logits stride (= 130*128)
#define KNN_  6
#define BM    128
#define KC    32             // f32 K-elements per pipeline chunk
#define LDA   40             // KC + 8 pad (conflict-free ldmatrix)
#define NCHUNK (D_ / KC)     // 64
#define NTILE  130           // ceil(C_/128)
#define NTHR  512

static __device__ float g_logits[B_ * CP];   // ~8.5 MB scratch
static __device__ float g_rowloss[B_];
static __device__ int   g_done = 0;

// SMEM: 3 stages x {A, B}, each 128 x LDA fp16 -> 61440 B dynamic
struct Smem {
    __half A[3][BM * LDA];
    __half Bm[3][BM * LDA];
};
#define SMEM_DYN (sizeof(Smem))

// ---------------------------------------------------------------------------
// Fused kernel: fp16 HMMA GEMM (logits = X·Emᵀ; x20 applied downstream)
//   + fused em -> out copy
//   + fused EMA memory-bank update for label rows owned by this tile.
// One CTA per 128-row em tile. 512 threads, 16 warps (4M x 4N of 32x32).
// 3-stage pipeline, single __syncthreads per K-chunk.
// ---------------------------------------------------------------------------
__global__ __launch_bounds__(NTHR, 1) void gemm_fused(const float* __restrict__ X,
                                                      const float* __restrict__ Em,
                                                      const int* __restrict__ label,
                                                      const int* __restrict__ epoch_p,
                                                      float* __restrict__ out1) {
    extern __shared__ char smraw[];
    Smem* sm = (Smem*)smraw;

    const int tid = threadIdx.x;
    const int wid = tid >> 5;
    const int c0  = blockIdx.x * BM;
    const int wm  = (wid & 3) * 32;    // warp M origin (em rows)
    const int wn  = (wid >> 2) * 32;   // warp N origin (batch)

    wmma::fragment<wmma::accumulator, 16, 16, 16, float> acc[2][2];
    #pragma unroll
    for (int i = 0; i < 2; i++)
        #pragma unroll
        for (int j = 0; j < 2; j++) wmma::fill_fragment(acc[i][j], 0.0f);

    float4 pf[4];   // prefetch: 4 float4 = 16 f32 per thread per chunk

    // global -> registers for one K-chunk (em tile rows + X rows)
    auto ldchunk = [&](int chunk) {
        const int k0 = chunk * KC;
        #pragma unroll
        for (int t = 0; t < 4; t++) {
            const int g   = tid + t * NTHR;    // 0..2047
            const int mat = g >> 10;           // 0 = A(em), 1 = B(X)
            const int idx = g & 1023;
            const int row = idx >> 3;          // 0..127
            const int q   = idx & 7;           // float4 quad
            if (mat == 0) {
                const int c = c0 + row;
                pf[t] = (c < C_) ? *(const float4*)(Em + (long long)c * D_ + k0 + q * 4)
                                 : make_float4(0.f, 0.f, 0.f, 0.f);
            } else {
                pf[t] = *(const float4*)(X + (long long)row * D_ + k0 + q * 4);
            }
        }
    };

    // registers -> smem fp16 + fused em copy to out
    auto stchunk = [&](int chunk, int st) {
        const int k0 = chunk * KC;
        #pragma unroll
        for (int t = 0; t < 4; t++) {
            const int g   = tid + t * NTHR;
            const int mat = g >> 10;
            const int idx = g & 1023;
            const int row = idx >> 3;
            const int q   = idx & 7;
            float4 f = pf[t];
            __half2 h0 = __float22half2_rn(make_float2(f.x, f.y));
            __half2 h1 = __float22half2_rn(make_float2(f.z, f.w));
            __half* hb = mat ? sm->Bm[st] : sm->A[st];
            const int so = row * LDA + q * 4;
            *(__half2*)(hb + so)     = h0;
            *(__half2*)(hb + so + 2) = h1;
            if (mat == 0 && c0 + row < C_) {
                float* o = out1 + (long long)(c0 + row) * D_ + k0 + q * 4;
                o[0] = f.x; o[1] = f.y; o[2] = f.z; o[3] = f.w;
            }
        }
    };

    // prologue: chunks 0,1 into stages 0,1
    ldchunk(0); stchunk(0, 0);
    ldchunk(1); stchunk(1, 1);
    __syncthreads();

    for (int s = 0; s < NCHUNK; s++) {
        const int st = s % 3;
        const bool more = (s + 2 < NCHUNK);
        if (more) ldchunk(s + 2);

        #pragma unroll
        for (int kk = 0; kk < KC; kk += 16) {
            wmma::fragment<wmma::matrix_a, 16, 16, 16, __half, wmma::row_major> af[2];
            wmma::fragment<wmma::matrix_b, 16, 16, 16, __half, wmma::col_major> bf[2];
            #pragma unroll
            for (int i = 0; i < 2; i++)
                wmma::load_matrix_sync(af[i], sm->A[st] + (wm + i * 16) * LDA + kk, LDA);
            #pragma unroll
            for (int j = 0; j < 2; j++)
                wmma::load_matrix_sync(bf[j], sm->Bm[st] + (wn + j * 16) * LDA + kk, LDA);
            #pragma unroll
            for (int i = 0; i < 2; i++)
                #pragma unroll
                for (int j = 0; j < 2; j++)
                    wmma::mma_sync(acc[i][j], af[i], bf[j], acc[i][j]);
        }

        if (more) stchunk(s + 2, (s + 2) % 3);   // stage untouched by current readers
        __syncthreads();
    }

    // logits store: D(m = em-row-local, n = batch) -> g_logits[n*CP + c0+m]
    #pragma unroll
    for (int i = 0; i < 2; i++)
        #pragma unroll
        for (int j = 0; j < 2; j++) {
            float* p = g_logits + (long long)(wn + j * 16) * CP + c0 + wm + i * 16;
            wmma::store_matrix_sync(p, acc[i][j], CP, wmma::mem_col_major);
        }

    // ---------------- fused EMA update for label rows in this tile ----------
    __shared__ int   lab[B_];
    __shared__ float red[17];
    if (tid < B_) lab[tid] = label[tid];
    __syncthreads();

    // does this tile own any label? (uniform decision)
    bool any = false;
    for (int b = 0; b < B_; b++)
        if (lab[b] >= c0 && lab[b] < c0 + BM) { any = true; break; }
    if (!any) return;

    const float alpha = 0.01f * (float)epoch_p[0];
    const int lane = tid & 31;

    for (int b = 0; b < B_; b++) {
        const int y = lab[b];
        if (y < c0 || y >= c0 + BM) continue;
        bool head = true;
        for (int j = 0; j < b; j++)
            if (lab[j] == y) { head = false; break; }
        if (!head) continue;

        float r[4];
        #pragma unroll
        for (int k = 0; k < 4; k++) r[k] = Em[(long long)y * D_ + k * NTHR + tid];

        for (int i = b; i < B_; i++) {
            if (lab[i] != y) continue;
            float sq = 0.f;
            #pragma unroll
            for (int k = 0; k < 4; k++) {
                r[k] = alpha * r[k] + (1.f - alpha) * X[i * D_ + k * NTHR + tid];
                sq = fmaf(r[k], r[k], sq);
            }
            #pragma unroll
            for (int o = 16; o > 0; o >>= 1) sq += __shfl_xor_sync(0xffffffffu, sq, o);
            if (lane == 0) red[wid] = sq;
            __syncthreads();
            if (tid == 0) {
                float tot = 0.f;
                #pragma unroll
                for (int w = 0; w < 16; w++) tot += red[w];
                red[16] = tot;
            }
            __syncthreads();
            float inv = rsqrtf(red[16]);
            __syncthreads();
            #pragma unroll
            for (int k = 0; k < 4; k++) r[k] *= inv;
        }

        #pragma unroll
        for (int k = 0; k < 4; k++) out1[(long long)y * D_ + k * NTHR + tid] = r[k];
    }
}

// ---------------------------------------------------------------------------
// Per-row logsumexp + top-6 + row loss; last block finalizes mean loss.
// One block per B-row; x20 scale at load.
// ---------------------------------------------------------------------------
__global__ __launch_bounds__(256) void row_reduce_kernel(const int* __restrict__ label,
                                                         float* __restrict__ loss_out) {
    const int b   = blockIdx.x;
    const int tid = threadIdx.x;
    const float* row = &g_logits[b * CP];

    float m = -INFINITY, s = 0.f;
    float tv[KNN_];
    int   ti[KNN_];
    #pragma unroll
    for (int j = 0; j < KNN_; j++) { tv[j] = -INFINITY; ti[j] = -1; }

    for (int c = tid; c < C_; c += 256) {
        float v = row[c] * 20.0f;
        if (v > m) { s = s * __expf(m - v) + 1.f; m = v; }
        else       { s += __expf(v - m); }
        if (v > tv[KNN_ - 1]) {
            int p = KNN_ - 1;
            while (p > 0 && v > tv[p - 1]) { tv[p] = tv[p - 1]; ti[p] = ti[p - 1]; p--; }
            tv[p] = v; ti[p] = c;
        }
    }

    __shared__ float sm[256], ss[256];
    __shared__ float cv[256 * KNN_];
    __shared__ int   ci[256 * KNN_];
    __shared__ float rv[256];
    __shared__ int   ri[256];
    __shared__ float out_tv[KNN_];
    __shared__ int   out_ti[KNN_];
    __shared__ int   is_last;

    sm[tid] = m; ss[tid] = s;
    #pragma unroll
    for (int j = 0; j < KNN_; j++) { cv[tid * KNN_ + j] = tv[j]; ci[tid * KNN_ + j] = ti[j]; }
    __syncthreads();

    for (int off = 128; off > 0; off >>= 1) {
        if (tid < off) {
            float m2 = sm[tid + off], s2 = ss[tid + off];
            float m1 = sm[tid],       s1 = ss[tid];
            float mm = fmaxf(m1, m2);
            ss[tid] = s1 * __expf(m1 - mm) + s2 * __expf(m2 - mm);
            sm[tid] = mm;
        }
        __syncthreads();
    }

    for (int r = 0; r < KNN_; r++) {
        float bm = -INFINITY; int bi = -1;
        #pragma unroll
        for (int j = 0; j < KNN_; j++) {
            float v = cv[tid * KNN_ + j];
            if (v > bm) { bm = v; bi = tid * KNN_ + j; }
        }
        rv[tid] = bm; ri[tid] = bi;
        __syncthreads();
        for (int off = 128; off > 0; off >>= 1) {
            if (tid < off && rv[tid + off] > rv[tid]) {
                rv[tid] = rv[tid + off]; ri[tid] = ri[tid + off];
            }
            __syncthreads();
        }
        if (tid == 0) {
            out_tv[r] = rv[0];
            out_ti[r] = ci[ri[0]];
            cv[ri[0]] = -INFINITY;
        }
        __syncthreads();
    }

    if (tid == 0) {
        float LSE  = sm[0] + logf(ss[0]);
        int   y    = label[b];
        float vlab = row[y] * 20.0f;
        float sum2 = 0.f;
        int   in   = 0;
        #pragma unroll
        for (int j = 0; j < KNN_; j++) {
            sum2 += (LSE - out_tv[j]);
            if (out_ti[j] == y) in = 1;
        }
        float ll = LSE - vlab;
        g_rowloss[b] = 2.f * sum2 + (3.f - 2.f * (float)in) * ll;
        __threadfence();
        is_last = (atomicAdd(&g_done, 1) == B_ - 1);
    }
    __syncthreads();

    if (is_last) {   // last-arriving block computes the mean loss
        __shared__ float sh[128];
        if (tid < 128) sh[tid] = g_rowloss[tid];
        __syncthreads();
        for (int off = 64; off > 0; off >>= 1) {
            if (tid < off && tid < 128) sh[tid] += sh[tid + off];
            __syncthreads();
        }
        if (tid == 0) {
            loss_out[0] = sh[0] / (float)B_;
            g_done = 0;                      // reset for next graph replay
        }
    }
}

// ---------------------------------------------------------------------------
// Launch
// ---------------------------------------------------------------------------
extern "C" void kernel_launch(void* const* d_in, const int* in_sizes, int n_in,
                              void* d_out, int out_size) {
    const float* X     = (const float*)d_in[0];  // [128, 2048] f32
    const int*   label = (const int*)  d_in[1];  // [128] i32
    const float* Em    = (const float*)d_in[2];  // [16522, 2048] f32
    const int*   epoch = (const int*)  d_in[3];  // scalar

    float* out = (float*)d_out;                  // [0]=loss, [1..]=em_new

    cudaFuncSetAttribute(gemm_fused, cudaFuncAttributeMaxDynamicSharedMemorySize, SMEM_DYN);

    gemm_fused       <<<NTILE, NTHR, SMEM_DYN>>>(X, Em, label, epoch, out + 1);
    row_reduce_kernel<<<B_, 256>>>(label, out);
}

// round 6
// speedup vs baseline: 1.2583x; 1.2583x over previous
#include <cuda_runtime.h>
#include <cuda_fp16.h>
#include <mma.h>
#include <math.h>
#include <stdint.h>

using namespace nvcuda;

// Problem constants
#define B_    128
#define D_    2048
#define C_    16522
#define CP    16640          // padded logits stride (= 130*128)
#define KNN_  6
#define BM    128
#define KC    64             // f32 K-elements per pipeline chunk
#define LDA   72             // KC + 8 pad (conflict-free ldmatrix)
#define NCHUNK (D_ / KC)     // 32
#define NTILE  130           // ceil(C_/128)
#define NTHR  512
#define RTHR  512            // row_reduce threads

static __device__ float g_logits[B_ * CP];   // ~8.5 MB scratch
static __device__ float g_rowloss[B_];
static __device__ int   g_done = 0;

// SMEM: 3 stages x {A, B}, each 128 x LDA fp16 -> 110592 B dynamic
struct Smem {
    __half A[3][BM * LDA];
    __half Bm[3][BM * LDA];
};
#define SMEM_DYN (sizeof(Smem))

// ---------------------------------------------------------------------------
// Fused kernel: fp16 HMMA GEMM (logits = X·Emᵀ; x20 applied downstream)
//   + fused em -> out copy (streaming stores)
//   + fused EMA memory-bank update for label rows owned by this tile.
// One CTA per 128-row em tile. 512 threads, 16 warps (4M x 4N of 32x32).
// KC=64: 32 chunks, 3-stage pipeline, ONE __syncthreads per chunk.
// ---------------------------------------------------------------------------
__global__ __launch_bounds__(NTHR, 1) void gemm_fused(const float* __restrict__ X,
                                                      const float* __restrict__ Em,
                                                      const int* __restrict__ label,
                                                      const int* __restrict__ epoch_p,
                                                      float* __restrict__ out1) {
    extern __shared__ char smraw[];
    Smem* sm = (Smem*)smraw;

    const int tid = threadIdx.x;
    const int wid = tid >> 5;
    const int c0  = blockIdx.x * BM;
    const int wm  = (wid & 3) * 32;    // warp M origin (em rows)
    const int wn  = (wid >> 2) * 32;   // warp N origin (batch)

    wmma::fragment<wmma::accumulator, 16, 16, 16, float> acc[2][2];
    #pragma unroll
    for (int i = 0; i < 2; i++)
        #pragma unroll
        for (int j = 0; j < 2; j++) wmma::fill_fragment(acc[i][j], 0.0f);

    float4 pf[8];   // prefetch: 8 float4 = 32 f32 per thread per chunk

    // global -> registers for one K-chunk (em tile rows + X rows)
    // layout: 256 rows x 16 quads; first 2048 quads = A(em), next 2048 = B(X)
    auto ldchunk = [&](int chunk) {
        const int k0 = chunk * KC;
        #pragma unroll
        for (int t = 0; t < 8; t++) {
            const int g   = tid + t * NTHR;     // 0..4095
            const int mat = g >> 11;            // 0 = A(em), 1 = B(X)
            const int idx = g & 2047;
            const int row = idx >> 4;           // 0..127
            const int q   = idx & 15;           // float4 quad within KC
            if (mat == 0) {
                const int c = c0 + row;
                pf[t] = (c < C_) ? __ldcs((const float4*)(Em + (long long)c * D_ + k0 + q * 4))
                                 : make_float4(0.f, 0.f, 0.f, 0.f);
            } else {
                pf[t] = *(const float4*)(X + (long long)row * D_ + k0 + q * 4);
            }
        }
    };

    // registers -> smem fp16 + fused em copy to out (streaming)
    auto stchunk = [&](int chunk, int st) {
        const int k0 = chunk * KC;
        #pragma unroll
        for (int t = 0; t < 8; t++) {
            const int g   = tid + t * NTHR;
            const int mat = g >> 11;
            const int idx = g & 2047;
            const int row = idx >> 4;
            const int q   = idx & 15;
            float4 f = pf[t];
            __half2 h0 = __float22half2_rn(make_float2(f.x, f.y));
            __half2 h1 = __float22half2_rn(make_float2(f.z, f.w));
            __half* hb = mat ? sm->Bm[st] : sm->A[st];
            const int so = row * LDA + q * 4;
            *(__half2*)(hb + so)     = h0;
            *(__half2*)(hb + so + 2) = h1;
            if (mat == 0 && c0 + row < C_) {
                float* o = out1 + (long long)(c0 + row) * D_ + k0 + q * 4;
                __stcs(o + 0, f.x); __stcs(o + 1, f.y);
                __stcs(o + 2, f.z); __stcs(o + 3, f.w);
            }
        }
    };

    // prologue: chunks 0,1 into stages 0,1
    ldchunk(0); stchunk(0, 0);
    ldchunk(1); stchunk(1, 1);
    __syncthreads();

    for (int s = 0; s < NCHUNK; s++) {
        const int st = s % 3;
        const bool more = (s + 2 < NCHUNK);
        if (more) ldchunk(s + 2);

        #pragma unroll
        for (int kk = 0; kk < KC; kk += 16) {
            wmma::fragment<wmma::matrix_a, 16, 16, 16, __half, wmma::row_major> af[2];
            wmma::fragment<wmma::matrix_b, 16, 16, 16, __half, wmma::col_major> bf[2];
            #pragma unroll
            for (int i = 0; i < 2; i++)
                wmma::load_matrix_sync(af[i], sm->A[st] + (wm + i * 16) * LDA + kk, LDA);
            #pragma unroll
            for (int j = 0; j < 2; j++)
                wmma::load_matrix_sync(bf[j], sm->Bm[st] + (wn + j * 16) * LDA + kk, LDA);
            #pragma unroll
            for (int i = 0; i < 2; i++)
                #pragma unroll
                for (int j = 0; j < 2; j++)
                    wmma::mma_sync(acc[i][j], af[i], bf[j], acc[i][j]);
        }

        if (more) stchunk(s + 2, (s + 2) % 3);   // stage idle since sync of iter s-1
        __syncthreads();
    }

    // logits store: D(m = em-row-local, n = batch) -> g_logits[n*CP + c0+m]
    #pragma unroll
    for (int i = 0; i < 2; i++)
        #pragma unroll
        for (int j = 0; j < 2; j++) {
            float* p = g_logits + (long long)(wn + j * 16) * CP + c0 + wm + i * 16;
            wmma::store_matrix_sync(p, acc[i][j], CP, wmma::mem_col_major);
        }

    // ---------------- fused EMA update for label rows in this tile ----------
    __shared__ int   lab[B_];
    __shared__ float red[17];
    if (tid < B_) lab[tid] = label[tid];
    __syncthreads();

    bool any = false;
    for (int b = 0; b < B_; b++)
        if (lab[b] >= c0 && lab[b] < c0 + BM) { any = true; break; }
    if (!any) return;

    const float alpha = 0.01f * (float)epoch_p[0];
    const int lane = tid & 31;

    for (int b = 0; b < B_; b++) {
        const int y = lab[b];
        if (y < c0 || y >= c0 + BM) continue;
        bool head = true;
        for (int j = 0; j < b; j++)
            if (lab[j] == y) { head = false; break; }
        if (!head) continue;

        float r[4];
        #pragma unroll
        for (int k = 0; k < 4; k++) r[k] = Em[(long long)y * D_ + k * NTHR + tid];

        for (int i = b; i < B_; i++) {
            if (lab[i] != y) continue;
            float sq = 0.f;
            #pragma unroll
            for (int k = 0; k < 4; k++) {
                r[k] = alpha * r[k] + (1.f - alpha) * X[i * D_ + k * NTHR + tid];
                sq = fmaf(r[k], r[k], sq);
            }
            #pragma unroll
            for (int o = 16; o > 0; o >>= 1) sq += __shfl_xor_sync(0xffffffffu, sq, o);
            if (lane == 0) red[wid] = sq;
            __syncthreads();
            if (tid == 0) {
                float tot = 0.f;
                #pragma unroll
                for (int w = 0; w < 16; w++) tot += red[w];
                red[16] = tot;
            }
            __syncthreads();
            float inv = rsqrtf(red[16]);
            __syncthreads();
            #pragma unroll
            for (int k = 0; k < 4; k++) r[k] *= inv;
        }

        #pragma unroll
        for (int k = 0; k < 4; k++) out1[(long long)y * D_ + k * NTHR + tid] = r[k];
    }
}

// ---------------------------------------------------------------------------
// Per-row logsumexp + top-6 + row loss (vectorized); last block finalizes.
// 512 threads/block, float4 loads, x20 scale at load.
// ---------------------------------------------------------------------------
__global__ __launch_bounds__(RTHR) void row_reduce_kernel(const int* __restrict__ label,
                                                          float* __restrict__ loss_out) {
    const int b   = blockIdx.x;
    const int tid = threadIdx.x;
    const float*  row  = &g_logits[b * CP];
    const float4* row4 = (const float4*)row;

    float m = -INFINITY, s = 0.f;
    float tv[KNN_];
    int   ti[KNN_];
    #pragma unroll
    for (int j = 0; j < KNN_; j++) { tv[j] = -INFINITY; ti[j] = -1; }

    auto insert1 = [&](float v, int c) {
        if (v > tv[KNN_ - 1]) {
            int p = KNN_ - 1;
            while (p > 0 && v > tv[p - 1]) { tv[p] = tv[p - 1]; ti[p] = ti[p - 1]; p--; }
            tv[p] = v; ti[p] = c;
        }
    };

    // 16520 / 4 = 4130 float4s; elements 16520, 16521 handled as tail
    for (int i = tid; i < 4130; i += RTHR) {
        float4 v = row4[i];
        v.x *= 20.0f; v.y *= 20.0f; v.z *= 20.0f; v.w *= 20.0f;
        float m4 = fmaxf(fmaxf(v.x, v.y), fmaxf(v.z, v.w));
        if (m4 > m) { s *= __expf(m - m4); m = m4; }
        s += __expf(v.x - m) + __expf(v.y - m) + __expf(v.z - m) + __expf(v.w - m);
        if (m4 > tv[KNN_ - 1]) {
            const int c = i * 4;
            insert1(v.x, c); insert1(v.y, c + 1);
            insert1(v.z, c + 2); insert1(v.w, c + 3);
        }
    }
    if (tid == 0) {
        #pragma unroll
        for (int c = 16520; c < C_; c++) {
            float v = row[c] * 20.0f;
            if (v > m) { s *= __expf(m - v); m = v; }
            s += __expf(v - m);
            insert1(v, c);
        }
    }

    __shared__ float sm[RTHR], ss[RTHR];
    __shared__ float cv[RTHR * KNN_];
    __shared__ int   ci[RTHR * KNN_];
    __shared__ float rv[RTHR];
    __shared__ int   ri[RTHR];
    __shared__ float out_tv[KNN_];
    __shared__ int   out_ti[KNN_];
    __shared__ int   is_last;

    sm[tid] = m; ss[tid] = s;
    #pragma unroll
    for (int j = 0; j < KNN_; j++) { cv[tid * KNN_ + j] = tv[j]; ci[tid * KNN_ + j] = ti[j]; }
    __syncthreads();

    for (int off = RTHR / 2; off > 0; off >>= 1) {
        if (tid < off) {
            float m2 = sm[tid + off], s2 = ss[tid + off];
            float m1 = sm[tid],       s1 = ss[tid];
            float mm = fmaxf(m1, m2);
            ss[tid] = s1 * __expf(m1 - mm) + s2 * __expf(m2 - mm);
            sm[tid] = mm;
        }
        __syncthreads();
    }

    for (int r = 0; r < KNN_; r++) {
        float bm = -INFINITY; int bi = -1;
        #pragma unroll
        for (int j = 0; j < KNN_; j++) {
            float v = cv[tid * KNN_ + j];
            if (v > bm) { bm = v; bi = tid * KNN_ + j; }
        }
        rv[tid] = bm; ri[tid] = bi;
        __syncthreads();
        for (int off = RTHR / 2; off > 0; off >>= 1) {
            if (tid < off && rv[tid + off] > rv[tid]) {
                rv[tid] = rv[tid + off]; ri[tid] = ri[tid + off];
            }
            __syncthreads();
        }
        if (tid == 0) {
            out_tv[r] = rv[0];
            out_ti[r] = ci[ri[0]];
            cv[ri[0]] = -INFINITY;
        }
        __syncthreads();
    }

    if (tid == 0) {
        float LSE  = sm[0] + logf(ss[0]);
        int   y    = label[b];
        float vlab = row[y] * 20.0f;
        float sum2 = 0.f;
        int   in   = 0;
        #pragma unroll
        for (int j = 0; j < KNN_; j++) {
            sum2 += (LSE - out_tv[j]);
            if (out_ti[j] == y) in = 1;
        }
        float ll = LSE - vlab;
        g_rowloss[b] = 2.f * sum2 + (3.f - 2.f * (float)in) * ll;
        __threadfence();
        is_last = (atomicAdd(&g_done, 1) == B_ - 1);
    }
    __syncthreads();

    if (is_last) {   // last-arriving block computes the mean loss
        __shared__ float sh[128];
        if (tid < 128) sh[tid] = g_rowloss[tid];
        __syncthreads();
        for (int off = 64; off > 0; off >>= 1) {
            if (tid < off && tid < 128) sh[tid] += sh[tid + off];
            __syncthreads();
        }
        if (tid == 0) {
            loss_out[0] = sh[0] / (float)B_;
            g_done = 0;                      // reset for next graph replay
        }
    }
}

// ---------------------------------------------------------------------------
// Launch
// ---------------------------------------------------------------------------
extern "C" void kernel_launch(void* const* d_in, const int* in_sizes, int n_in,
                              void* d_out, int out_size) {
    const float* X     = (const float*)d_in[0];  // [128, 2048] f32
    const int*   label = (const int*)  d_in[1];  // [128] i32
    const float* Em    = (const float*)d_in[2];  // [16522, 2048] f32
    const int*   epoch = (const int*)  d_in[3];  // scalar

    float* out = (float*)d_out;                  // [0]=loss, [1..]=em_new

    cudaFuncSetAttribute(gemm_fused, cudaFuncAttributeMaxDynamicSharedMemorySize, SMEM_DYN);

    gemm_fused       <<<NTILE, NTHR, SMEM_DYN>>>(X, Em, label, epoch, out + 1);
    row_reduce_kernel<<<B_, RTHR>>>(label, out);
}

// round 7
// speedup vs baseline: 1.2622x; 1.0031x over previous
#include <cuda_runtime.h>
#include <cuda_fp16.h>
#include <mma.h>
#include <math.h>
#include <stdint.h>

using namespace nvcuda;

// Problem constants
#define B_    128
#define D_    2048
#define C_    16522
#define KNN_  6
#define BM    128
#define KC    64             // f32 K-elements per pipeline chunk
#define LDA   72             // KC + 8 pad (conflict-free ldmatrix)
#define LDE   136            // epilogue smem row stride (128 + 8 floats)
#define NCHUNK (D_ / KC)     // 32
#define NTILE  130           // ceil(C_/128)
#define NTHR  512

// Per-tile softmax partials (logits scratch eliminated)
static __device__ float g_pm[B_ * NTILE];            // tile max per (row, tile)
static __device__ float g_ps[B_ * NTILE];            // tile sum-exp (rel. tile max)
static __device__ float g_tv6[B_ * NTILE * KNN_];    // tile top-6 values
static __device__ int   g_ti6[B_ * NTILE * KNN_];    // tile top-6 global indices
static __device__ float g_vlab[B_];                  // logit at true label (x20)
static __device__ float g_rowloss[B_];
static __device__ int   g_done = 0;

// SMEM: 3 stages x {A, B}, each 128 x LDA fp16 -> 110592 B dynamic.
// Epilogue reuses the same dynamic smem as LT[128 rows][LDE] f32 (69632 B).
struct Smem {
    __half A[3][BM * LDA];
    __half Bm[3][BM * LDA];
};
#define SMEM_DYN (sizeof(Smem))

// ---------------------------------------------------------------------------
// Fused kernel: fp16 HMMA GEMM (logits = X·Emᵀ x20)
//   + fused em -> out copy (streaming stores)
//   + per-tile partial softmax / top-6 epilogue (h2exp)
//   + fused EMA memory-bank update for label rows owned by this tile.
// One CTA per 128-row em tile. 512 threads, 16 warps (4M x 4N of 32x32).
// ---------------------------------------------------------------------------
__global__ __launch_bounds__(NTHR, 1) void gemm_fused(const float* __restrict__ X,
                                                      const float* __restrict__ Em,
                                                      const int* __restrict__ label,
                                                      const int* __restrict__ epoch_p,
                                                      float* __restrict__ out1) {
    extern __shared__ char smraw[];
    Smem* sm = (Smem*)smraw;

    const int tid = threadIdx.x;
    const int wid = tid >> 5;
    const int bt  = blockIdx.x;
    const int c0  = bt * BM;
    const int wm  = (wid & 3) * 32;    // warp M origin (em rows / classes)
    const int wn  = (wid >> 2) * 32;   // warp N origin (batch)

    wmma::fragment<wmma::accumulator, 16, 16, 16, float> acc[2][2];
    #pragma unroll
    for (int i = 0; i < 2; i++)
        #pragma unroll
        for (int j = 0; j < 2; j++) wmma::fill_fragment(acc[i][j], 0.0f);

    float4 pf[8];

    auto ldchunk = [&](int chunk) {
        const int k0 = chunk * KC;
        #pragma unroll
        for (int t = 0; t < 8; t++) {
            const int g   = tid + t * NTHR;     // 0..4095
            const int mat = g >> 11;            // 0 = A(em), 1 = B(X)
            const int idx = g & 2047;
            const int row = idx >> 4;           // 0..127
            const int q   = idx & 15;
            if (mat == 0) {
                const int c = c0 + row;
                pf[t] = (c < C_) ? __ldcs((const float4*)(Em + (long long)c * D_ + k0 + q * 4))
                                 : make_float4(0.f, 0.f, 0.f, 0.f);
            } else {
                pf[t] = *(const float4*)(X + (long long)row * D_ + k0 + q * 4);
            }
        }
    };

    auto stchunk = [&](int chunk, int st) {
        const int k0 = chunk * KC;
        #pragma unroll
        for (int t = 0; t < 8; t++) {
            const int g   = tid + t * NTHR;
            const int mat = g >> 11;
            const int idx = g & 2047;
            const int row = idx >> 4;
            const int q   = idx & 15;
            float4 f = pf[t];
            __half2 h0 = __float22half2_rn(make_float2(f.x, f.y));
            __half2 h1 = __float22half2_rn(make_float2(f.z, f.w));
            __half* hb = mat ? sm->Bm[st] : sm->A[st];
            const int so = row * LDA + q * 4;
            *(__half2*)(hb + so)     = h0;
            *(__half2*)(hb + so + 2) = h1;
            if (mat == 0 && c0 + row < C_) {
                float* o = out1 + (long long)(c0 + row) * D_ + k0 + q * 4;
                __stcs(o + 0, f.x); __stcs(o + 1, f.y);
                __stcs(o + 2, f.z); __stcs(o + 3, f.w);
            }
        }
    };

    ldchunk(0); stchunk(0, 0);
    ldchunk(1); stchunk(1, 1);
    __syncthreads();

    for (int s = 0; s < NCHUNK; s++) {
        const int st = s % 3;
        const bool more = (s + 2 < NCHUNK);
        if (more) ldchunk(s + 2);

        #pragma unroll
        for (int kk = 0; kk < KC; kk += 16) {
            wmma::fragment<wmma::matrix_a, 16, 16, 16, __half, wmma::row_major> af[2];
            wmma::fragment<wmma::matrix_b, 16, 16, 16, __half, wmma::col_major> bf[2];
            #pragma unroll
            for (int i = 0; i < 2; i++)
                wmma::load_matrix_sync(af[i], sm->A[st] + (wm + i * 16) * LDA + kk, LDA);
            #pragma unroll
            for (int j = 0; j < 2; j++)
                wmma::load_matrix_sync(bf[j], sm->Bm[st] + (wn + j * 16) * LDA + kk, LDA);
            #pragma unroll
            for (int i = 0; i < 2; i++)
                #pragma unroll
                for (int j = 0; j < 2; j++)
                    wmma::mma_sync(acc[i][j], af[i], bf[j], acc[i][j]);
        }

        if (more) stchunk(s + 2, (s + 2) % 3);
        __syncthreads();
    }

    // ================= epilogue: tile -> smem batch-major ==================
    __shared__ int   lab[B_];
    __shared__ float red[17];
    __shared__ float tvv[NTHR][KNN_];
    __shared__ int   tii[NTHR][KNN_];

    if (tid < B_) lab[tid] = label[tid];

    float* LT = (float*)smraw;   // LT[n][c] = D(c, n), stride LDE
    #pragma unroll
    for (int i = 0; i < 2; i++)
        #pragma unroll
        for (int j = 0; j < 2; j++)
            wmma::store_matrix_sync(LT + (wn + j * 16) * LDE + (wm + i * 16),
                                    acc[i][j], LDE, wmma::mem_col_major);
    __syncthreads();

    if (c0 + BM > C_) {   // mask invalid class columns (last tile only)
        for (int idx = tid; idx < BM * B_; idx += NTHR) {
            int c = idx & 127, n = idx >> 7;
            if (c0 + c >= C_) LT[n * LDE + c] = -INFINITY;
        }
        __syncthreads();
    }

    // -------- per-thread partial over 32 classes of one batch row ----------
    {
        const int n   = tid >> 2;
        const int seg = tid & 3;
        const float* src = LT + n * LDE + seg * 32;

        float v[32];
        #pragma unroll
        for (int q = 0; q < 8; q++) {
            float4 f = *(const float4*)(src + q * 4);
            v[q * 4 + 0] = f.x * 20.0f; v[q * 4 + 1] = f.y * 20.0f;
            v[q * 4 + 2] = f.z * 20.0f; v[q * 4 + 3] = f.w * 20.0f;
        }

        float mt = -INFINITY;
        #pragma unroll
        for (int k = 0; k < 32; k++) mt = fmaxf(mt, v[k]);

        float st_ = 0.f;
        if (mt > -INFINITY) {
            #pragma unroll
            for (int k = 0; k < 32; k += 2) {
                __half2 e = h2exp(__floats2half2_rn(v[k] - mt, v[k + 1] - mt));
                float2 ef = __half22float2(e);
                st_ += ef.x + ef.y;
            }
        }

        float tv[KNN_]; int ti[KNN_];
        #pragma unroll
        for (int j = 0; j < KNN_; j++) { tv[j] = -INFINITY; ti[j] = -1; }
        #pragma unroll
        for (int k = 0; k < 32; k++) {
            float x = v[k];
            if (x > tv[KNN_ - 1]) {
                int p = KNN_ - 1;
                while (p > 0 && x > tv[p - 1]) { tv[p] = tv[p - 1]; ti[p] = ti[p - 1]; p--; }
                tv[p] = x; ti[p] = seg * 32 + k;
            }
        }

        // merge (m, s) across the 4 seg-threads of this row (same warp)
        float m_ = mt, s_ = st_;
        #pragma unroll
        for (int o = 1; o <= 2; o <<= 1) {
            float mo = __shfl_xor_sync(0xffffffffu, m_, o);
            float so = __shfl_xor_sync(0xffffffffu, s_, o);
            float mm = fmaxf(m_, mo);
            float a = (s_ > 0.f) ? s_ * __expf(m_ - mm) : 0.f;
            float b2 = (so > 0.f) ? so * __expf(mo - mm) : 0.f;
            m_ = mm; s_ = a + b2;
        }

        #pragma unroll
        for (int j = 0; j < KNN_; j++) { tvv[tid][j] = tv[j]; tii[tid][j] = ti[j]; }
        __syncthreads();

        if (seg == 0) {
            // merge 4 descending lists -> global top-6
            int p[4] = {0, 0, 0, 0};
            float otv[KNN_]; int oti[KNN_];
            #pragma unroll
            for (int r = 0; r < KNN_; r++) {
                float bv = -INFINITY; int bs = -1;
                #pragma unroll
                for (int q = 0; q < 4; q++) {
                    if (p[q] < KNN_) {
                        float cv_ = tvv[tid + q][p[q]];
                        if (cv_ > bv) { bv = cv_; bs = q; }
                    }
                }
                otv[r] = bv;
                oti[r] = (bs >= 0) ? c0 + tii[tid + bs][p[bs]] : -1;
                if (bs >= 0) p[bs]++;
            }
            const int o = n * NTILE + bt;
            g_pm[o] = m_;
            g_ps[o] = s_;
            #pragma unroll
            for (int j = 0; j < KNN_; j++) { g_tv6[o * KNN_ + j] = otv[j]; g_ti6[o * KNN_ + j] = oti[j]; }

            const int y = lab[n];
            if (y >= c0 && y < c0 + BM)
                g_vlab[n] = LT[n * LDE + (y - c0)] * 20.0f;
        }
    }
    __syncthreads();

    // ---------------- fused EMA update for label rows in this tile ----------
    bool any = false;
    for (int b = 0; b < B_; b++)
        if (lab[b] >= c0 && lab[b] < c0 + BM) { any = true; break; }
    if (!any) return;

    const float alpha = 0.01f * (float)epoch_p[0];
    const int lane = tid & 31;

    for (int b = 0; b < B_; b++) {
        const int y = lab[b];
        if (y < c0 || y >= c0 + BM) continue;
        bool head = true;
        for (int j = 0; j < b; j++)
            if (lab[j] == y) { head = false; break; }
        if (!head) continue;

        float r[4];
        #pragma unroll
        for (int k = 0; k < 4; k++) r[k] = Em[(long long)y * D_ + k * NTHR + tid];

        for (int i = b; i < B_; i++) {
            if (lab[i] != y) continue;
            float sq = 0.f;
            #pragma unroll
            for (int k = 0; k < 4; k++) {
                r[k] = alpha * r[k] + (1.f - alpha) * X[i * D_ + k * NTHR + tid];
                sq = fmaf(r[k], r[k], sq);
            }
            #pragma unroll
            for (int o = 16; o > 0; o >>= 1) sq += __shfl_xor_sync(0xffffffffu, sq, o);
            if (lane == 0) red[wid] = sq;
            __syncthreads();
            if (tid == 0) {
                float tot = 0.f;
                #pragma unroll
                for (int w = 0; w < 16; w++) tot += red[w];
                red[16] = tot;
            }
            __syncthreads();
            float inv = rsqrtf(red[16]);
            __syncthreads();
            #pragma unroll
            for (int k = 0; k < 4; k++) r[k] *= inv;
        }

        #pragma unroll
        for (int k = 0; k < 4; k++) out1[(long long)y * D_ + k * NTHR + tid] = r[k];
    }
}

// ---------------------------------------------------------------------------
// Combine: merge 130 tile-partials per batch row -> LSE, top-6, row loss.
// One block per row; last-arriving block computes the mean loss.
// ---------------------------------------------------------------------------
__global__ __launch_bounds__(256) void combine_kernel(const int* __restrict__ label,
                                                      float* __restrict__ loss_out) {
    const int b   = blockIdx.x;
    const int tid = threadIdx.x;

    float m = -INFINITY, s = 0.f;
    float tv[KNN_]; int ti[KNN_];
    #pragma unroll
    for (int j = 0; j < KNN_; j++) { tv[j] = -INFINITY; ti[j] = -1; }

    if (tid < NTILE) {
        const int o = b * NTILE + tid;
        m = g_pm[o];
        s = g_ps[o];
        #pragma unroll
        for (int j = 0; j < KNN_; j++) { tv[j] = g_tv6[o * KNN_ + j]; ti[j] = g_ti6[o * KNN_ + j]; }
    }

    __shared__ float sm_[256], ss_[256];
    __shared__ float cv[256 * KNN_];
    __shared__ int   ci[256 * KNN_];
    __shared__ float rv[256];
    __shared__ int   ri[256];
    __shared__ float out_tv[KNN_];
    __shared__ int   out_ti[KNN_];
    __shared__ int   is_last;

    sm_[tid] = m; ss_[tid] = s;
    #pragma unroll
    for (int j = 0; j < KNN_; j++) { cv[tid * KNN_ + j] = tv[j]; ci[tid * KNN_ + j] = ti[j]; }
    __syncthreads();

    for (int off = 128; off > 0; off >>= 1) {
        if (tid < off) {
            float m2 = sm_[tid + off], s2 = ss_[tid + off];
            float m1 = sm_[tid],       s1 = ss_[tid];
            float mm = fmaxf(m1, m2);
            float a = (s1 > 0.f) ? s1 * __expf(m1 - mm) : 0.f;
            float c = (s2 > 0.f) ? s2 * __expf(m2 - mm) : 0.f;
            ss_[tid] = a + c;
            sm_[tid] = mm;
        }
        __syncthreads();
    }

    for (int r = 0; r < KNN_; r++) {
        float bm = -INFINITY; int bi = -1;
        #pragma unroll
        for (int j = 0; j < KNN_; j++) {
            float v = cv[tid * KNN_ + j];
            if (v > bm) { bm = v; bi = tid * KNN_ + j; }
        }
        rv[tid] = bm; ri[tid] = bi;
        __syncthreads();
        for (int off = 128; off > 0; off >>= 1) {
            if (tid < off && rv[tid + off] > rv[tid]) {
                rv[tid] = rv[tid + off]; ri[tid] = ri[tid + off];
            }
            __syncthreads();
        }
        if (tid == 0) {
            out_tv[r] = rv[0];
            out_ti[r] = ci[ri[0]];
            cv[ri[0]] = -INFINITY;
        }
        __syncthreads();
    }

    if (tid == 0) {
        float LSE  = sm_[0] + logf(ss_[0]);
        int   y    = label[b];
        float vlab = g_vlab[b];
        float sum2 = 0.f;
        int   in   = 0;
        #pragma unroll
        for (int j = 0; j < KNN_; j++) {
            sum2 += (LSE - out_tv[j]);
            if (out_ti[j] == y) in = 1;
        }
        float ll = LSE - vlab;
        g_rowloss[b] = 2.f * sum2 + (3.f - 2.f * (float)in) * ll;
        __threadfence();
        is_last = (atomicAdd(&g_done, 1) == B_ - 1);
    }
    __syncthreads();

    if (is_last) {
        __shared__ float sh[128];
        if (tid < 128) sh[tid] = g_rowloss[tid];
        __syncthreads();
        for (int off = 64; off > 0; off >>= 1) {
            if (tid < off) sh[tid] += sh[tid + off];
            __syncthreads();
        }
        if (tid == 0) {
            loss_out[0] = sh[0] / (float)B_;
            g_done = 0;
        }
    }
}

// ---------------------------------------------------------------------------
// Launch
// ---------------------------------------------------------------------------
extern "C" void kernel_launch(void* const* d_in, const int* in_sizes, int n_in,
                              void* d_out, int out_size) {
    const float* X     = (const float*)d_in[0];  // [128, 2048] f32
    const int*   label = (const int*)  d_in[1];  // [128] i32
    const float* Em    = (const float*)d_in[2];  // [16522, 2048] f32
    const int*   epoch = (const int*)  d_in[3];  // scalar

    float* out = (float*)d_out;                  // [0]=loss, [1..]=em_new

    cudaFuncSetAttribute(gemm_fused, cudaFuncAttributeMaxDynamicSharedMemorySize, SMEM_DYN);

    gemm_fused    <<<NTILE, NTHR, SMEM_DYN>>>(X, Em, label, epoch, out + 1);
    combine_kernel<<<B_, 256>>>(label, out);
}